// round 10
// baseline (speedup 1.0000x reference)
#include <cuda_runtime.h>
#include <cstdint>

#define NROWS 8192
#define DDIM  128
#define NCLS  1000
#define KSPLIT 2
#define KRANGE (NROWS/KSPLIT)  // 4096
#define KCH   32
#define NCHUNK (KRANGE/KCH)    // 128
#define NSTAGE 4
#define APAD  40               // floats per smem row (32 + 8 pad): LDS.64 frag pattern conflict-free
#define TILE_B (128*APAD*4)    // 20480 B per stage per operand
#define OFF_B   (NSTAGE*TILE_B)       // 81920
#define DYN_BYTES (2*NSTAGE*TILE_B)   // 163840
#define NGEMM 128              // 64 mtiles x 2 ksplits
#define NCE   20
#define NTHR  512

__device__ __align__(16) float g_XT[(size_t)DDIM*NROWS];  // tf32-rounded X^T [d][j]
__device__ float  g_sq[NROWS];
__device__ double g_acc[3];   // 0: ce-sum  1: T  2: cross

// ---------------- helpers ----------------
__device__ __forceinline__ uint32_t smem_u32(const void* p){
    uint32_t a;
    asm("{ .reg .u64 t; cvta.to.shared.u64 t, %1; cvt.u32.u64 %0, t; }" : "=r"(a) : "l"(p));
    return a;
}
__device__ __forceinline__ uint32_t f2tf32(float x){
    uint32_t u;
    asm("cvt.rna.tf32.f32 %0, %1;" : "=r"(u) : "f"(x));
    return u;
}
__device__ __forceinline__ void lds64(uint32_t a, uint32_t& lo, uint32_t& hi){
    asm volatile("ld.shared.v2.b32 {%0,%1}, [%2];" : "=r"(lo), "=r"(hi) : "r"(a));
}
__device__ __forceinline__ float4 lds128f(uint32_t a){
    float4 v;
    asm volatile("ld.shared.v4.f32 {%0,%1,%2,%3}, [%4];"
                 : "=f"(v.x), "=f"(v.y), "=f"(v.z), "=f"(v.w) : "r"(a));
    return v;
}
__device__ __forceinline__ void cp16(uint32_t dst, const void* src){
    asm volatile("cp.async.cg.shared.global [%0], [%1], 16;" :: "r"(dst), "l"(src));
}
__device__ __forceinline__ void mma_tf32(float* c,
                                         uint32_t a0, uint32_t a1, uint32_t a2, uint32_t a3,
                                         uint32_t b0, uint32_t b1){
    asm volatile(
        "mma.sync.aligned.m16n8k8.row.col.f32.tf32.tf32.f32 "
        "{%0,%1,%2,%3}, {%4,%5,%6,%7}, {%8,%9}, {%0,%1,%2,%3};"
        : "+f"(c[0]), "+f"(c[1]), "+f"(c[2]), "+f"(c[3])
        : "r"(a0), "r"(a1), "r"(a2), "r"(a3), "r"(b0), "r"(b1));
}

// ---------------- prep: zero acc, sq[j] exact, XT tf32 ----------------
__global__ void __launch_bounds__(256) k_prep(const float* __restrict__ X){
    __shared__ float tile[64*129];
    int tid = threadIdx.x;
    int j0 = blockIdx.x * 64;
    if (blockIdx.x == 0 && tid < 3) g_acc[tid] = 0.0;
#pragma unroll
    for (int p = 0; p < 8; ++p){
        int idx = p*256 + tid;
        int r = idx >> 5;
        int c = idx & 31;
        float4 v = ((const float4*)(X + (size_t)(j0 + r)*DDIM))[c];
        tile[r*129 + c*4 + 0] = v.x;
        tile[r*129 + c*4 + 1] = v.y;
        tile[r*129 + c*4 + 2] = v.z;
        tile[r*129 + c*4 + 3] = v.w;
    }
    __syncthreads();
    if (tid < 64){
        float s = 0.f;
        const float* row = tile + tid*129;
#pragma unroll 8
        for (int c = 0; c < 128; ++c) s += row[c]*row[c];
        g_sq[j0 + tid] = s;
    }
#pragma unroll
    for (int p = 0; p < 8; ++p){
        int u  = p*256 + tid;
        int d  = u >> 4;
        int ju = (u & 15) * 4;
        uint4 o;
        o.x = f2tf32(tile[(ju+0)*129 + d]);
        o.y = f2tf32(tile[(ju+1)*129 + d]);
        o.z = f2tf32(tile[(ju+2)*129 + d]);
        o.w = f2tf32(tile[(ju+3)*129 + d]);
        *(uint4*)(g_XT + (size_t)d*NROWS + j0 + ju) = o;
    }
}

// ---------------- main: GEMM blocks 0..127, CE blocks 128..147 ----------------
__global__ void __launch_bounds__(NTHR, 1)
k_main(const float* __restrict__ L, const float* __restrict__ X,
       const float* __restrict__ preds, const int* __restrict__ tgt){
    extern __shared__ __align__(16) char dyn[];
    __shared__ float s_red[32];
    int tid = threadIdx.x, wid = tid>>5, lane = tid&31;

    if (blockIdx.x >= NGEMM){
        // ---- cross-entropy: 20 CTAs x 16 warps ----
        int g = (blockIdx.x - NGEMM)*16 + wid;     // 0..319
        float ce = 0.f;
        for (int r = g; r < NROWS; r += NCE*16){
            const float4* row4 = (const float4*)(preds + (size_t)r*NCLS);
            float s = 0.f;
            for (int c4 = lane; c4 < NCLS/4; c4 += 32){
                float4 v = __ldg(row4 + c4);
                s += __expf(v.x) + __expf(v.y) + __expf(v.z) + __expf(v.w);
            }
#pragma unroll
            for (int o = 16; o; o >>= 1) s += __shfl_xor_sync(~0u, s, o);
            if (lane == 0)
                ce += __logf(s) - __ldg(preds + (size_t)r*NCLS + __ldg(tgt + r));
        }
        if (lane == 0) atomicAdd(&g_acc[0], (double)ce);
        return;
    }

    // ---- GEMM + fused T ----
    uint32_t base = smem_u32(dyn);
    int m0 = (blockIdx.x >> 1) * 128;
    int k0 = (blockIdx.x & 1) * KRANGE;

    // loader mapping: 512 threads, row = tid>>2 (0..127), slots ls and ls+4 (16B each)
    int lrow = tid >> 2, ls = tid & 3;
    const float* Ap  = L    + (size_t)(m0 + lrow)*NROWS + k0;
    const float* Bp  = g_XT + (size_t)lrow*NROWS       + k0;
    const float* sqp = g_sq + k0;
    float my_sqm = __ldg(g_sq + m0 + lrow);
    uint32_t aoff = (uint32_t)(lrow*APAD)*4;

    // prologue: stages 0..NSTAGE-2
#pragma unroll
    for (int s = 0; s < NSTAGE-1; ++s){
        uint32_t da = base + s*TILE_B + aoff;
        uint32_t db = da + OFF_B;
        int kb = s*KCH;
        cp16(da + ls*16,      Ap + kb + ls*4);
        cp16(da + (ls+4)*16,  Ap + kb + (ls+4)*4);
        cp16(db + ls*16,      Bp + kb + ls*4);
        cp16(db + (ls+4)*16,  Bp + kb + (ls+4)*4);
        asm volatile("cp.async.commit_group;" ::: "memory");
    }

    // warp tiling: 4 (M) x 4 (N) warps; warp tile 32x32
    int warp_m = wid >> 2, warp_n = wid & 3;
    int r = lane >> 2, cg = lane & 3;
    uint32_t aA = base + (uint32_t)((warp_m*32 + r)*APAD + 2*cg)*4;
    uint32_t aB = base + OFF_B + (uint32_t)((warp_n*32 + r)*APAD + 2*cg)*4;

    float acc[2][4][4];
#pragma unroll
    for (int i = 0; i < 2; ++i)
#pragma unroll
        for (int j = 0; j < 4; ++j)
#pragma unroll
            for (int q = 0; q < 4; ++q) acc[i][j][q] = 0.f;
    float tloc = 0.f;

#pragma unroll 1
    for (int c = 0; c < NCHUNK; ++c){
        asm volatile("cp.async.wait_group %0;" :: "n"(NSTAGE-2) : "memory");
        __syncthreads();

        // stage c+NSTAGE-1 (buf (c-1)%NSTAGE, fully consumed before this barrier)
        int cn = c + NSTAGE - 1;
        if (cn < NCHUNK){
            uint32_t da = base + (cn & (NSTAGE-1))*TILE_B + aoff;
            uint32_t db = da + OFF_B;
            int kb = cn*KCH;
            cp16(da + ls*16,      Ap + kb + ls*4);
            cp16(da + (ls+4)*16,  Ap + kb + (ls+4)*4);
            cp16(db + ls*16,      Bp + kb + ls*4);
            cp16(db + (ls+4)*16,  Bp + kb + (ls+4)*4);
        }
        asm volatile("cp.async.commit_group;" ::: "memory");

        int buf = c & (NSTAGE-1);

        // fused T: read back this thread's raw L values from smem; sq via LDG (L1/L2-hot)
        {
            uint32_t ta = base + buf*TILE_B + aoff;
            float4 v0 = lds128f(ta + ls*16);
            float4 v1 = lds128f(ta + (ls+4)*16);
            float4 s0 = __ldg((const float4*)(sqp + c*KCH) + ls);
            float4 s1 = __ldg((const float4*)(sqp + c*KCH) + ls + 4);
            tloc += (v0.x+v0.y+v0.z+v0.w + v1.x+v1.y+v1.z+v1.w)*my_sqm
                  + v0.x*s0.x + v0.y*s0.y + v0.z*s0.z + v0.w*s0.w
                  + v1.x*s1.x + v1.y*s1.y + v1.z*s1.z + v1.w*s1.w;
        }

        // MMA over buffer c. A = raw fp32 bits (HW truncates to tf32).
        // k-permutation: MMA slot label cg -> physical k 2cg, label cg+4 -> 2cg+1;
        // applied to BOTH A and B, so the k-sum is unchanged and frags load as LDS.64.
        uint32_t bA = aA + buf*TILE_B;
        uint32_t bB = aB + buf*TILE_B;
#pragma unroll
        for (int k8 = 0; k8 < KCH; k8 += 8){
            uint32_t af[2][4], bf[4][2];
#pragma unroll
            for (int tm = 0; tm < 2; ++tm){
                uint32_t p = bA + (uint32_t)(tm*16*APAD + k8)*4;
                lds64(p,              af[tm][0], af[tm][2]);
                lds64(p + 8*APAD*4,   af[tm][1], af[tm][3]);
            }
#pragma unroll
            for (int tn = 0; tn < 4; ++tn){
                uint32_t p = bB + (uint32_t)(tn*8*APAD + k8)*4;
                lds64(p, bf[tn][0], bf[tn][1]);
            }
#pragma unroll
            for (int tm = 0; tm < 2; ++tm)
#pragma unroll
                for (int tn = 0; tn < 4; ++tn)
                    mma_tf32(acc[tm][tn], af[tm][0], af[tm][1], af[tm][2], af[tm][3],
                             bf[tn][0], bf[tn][1]);
        }
    }

    // epilogue: cross += acc .* X (exact fp32); D-fragment layout unaffected by k-permutation
    float cpart = 0.f;
#pragma unroll
    for (int tm = 0; tm < 2; ++tm){
#pragma unroll
        for (int tn = 0; tn < 4; ++tn){
#pragma unroll
            for (int q = 0; q < 4; ++q){
                int mrow = m0 + warp_m*32 + tm*16 + r + ((q>>1)<<3);
                int ncol = warp_n*32 + tn*8 + cg*2 + (q&1);
                cpart += acc[tm][tn][q] * __ldg(X + (size_t)mrow*DDIM + ncol);
            }
        }
    }

#pragma unroll
    for (int o = 16; o; o >>= 1){
        tloc  += __shfl_xor_sync(~0u, tloc,  o);
        cpart += __shfl_xor_sync(~0u, cpart, o);
    }
    if (lane == 0){ s_red[wid] = tloc; s_red[16 + wid] = cpart; }
    __syncthreads();
    if (tid == 0){
        float ts = 0.f, cs = 0.f;
#pragma unroll
        for (int w = 0; w < 16; ++w){ ts += s_red[w]; cs += s_red[16 + w]; }
        atomicAdd(&g_acc[1], (double)ts);
        atomicAdd(&g_acc[2], (double)cs);
    }
}

__global__ void k_final(float* out, int n){
    double v = g_acc[0] / (double)NROWS + 0.1 * (g_acc[1] - 2.0 * g_acc[2]);
    for (int i = threadIdx.x; i < n; i += blockDim.x) out[i] = (float)v;
}

extern "C" void kernel_launch(void* const* d_in, const int* in_sizes, int n_in,
                              void* d_out, int out_size){
    const float* preds = (const float*)d_in[0];
    const int*   tgt   = (const int*)d_in[1];
    const float* L     = (const float*)d_in[2];
    const float* X     = (const float*)d_in[3];
    float* out = (float*)d_out;
    (void)in_sizes; (void)n_in;

    cudaFuncSetAttribute((const void*)k_main, cudaFuncAttributeMaxDynamicSharedMemorySize, DYN_BYTES);

    k_prep<<<NROWS/64, 256>>>(X);
    k_main<<<NGEMM + NCE, NTHR, DYN_BYTES>>>(L, X, preds, tgt);
    k_final<<<1, 256>>>(out, out_size);
}

// round 12
// speedup vs baseline: 1.2392x; 1.2392x over previous
#include <cuda_runtime.h>
#include <cstdint>

#define NROWS 8192
#define DDIM  128
#define NCLS  1000
#define KSPLIT 2
#define KRANGE (NROWS/KSPLIT)  // 4096
#define KCH   64
#define NCHUNK (KRANGE/KCH)    // 64
#define NSTAGE 3
// A smem: k-major, 64 k-rows x 136 floats (128 m + 8 pad) = 544B/row -> 34816B
#define ASTRIDE 136
#define ABYTES  (KCH*ASTRIDE*4)
// B smem: d-major, 128 d-rows x 68 floats (64 k + 4 pad) = 272B/row -> 34816B
#define BSTRIDE 68
#define BBYTES  (128*BSTRIDE*4)
#define STAGEB  (ABYTES + BBYTES)       // 69632
#define DYN_BYTES (NSTAGE*STAGEB)       // 208896
#define NGEMM 128              // 64 mtiles x 2 ksplits
#define NCE   20
#define NTHR  512

__device__ __align__(16) float g_XT[(size_t)DDIM*NROWS];  // tf32-rounded X^T [d][j]
__device__ float  g_sq[NROWS];
__device__ double g_acc[3];   // 0: ce-sum  1: T  2: cross

// ---------------- helpers ----------------
__device__ __forceinline__ uint32_t smem_u32(const void* p){
    uint32_t a;
    asm("{ .reg .u64 t; cvta.to.shared.u64 t, %1; cvt.u32.u64 %0, t; }" : "=r"(a) : "l"(p));
    return a;
}
__device__ __forceinline__ uint32_t f2tf32(float x){
    uint32_t u;
    asm("cvt.rna.tf32.f32 %0, %1;" : "=r"(u) : "f"(x));
    return u;
}
__device__ __forceinline__ uint32_t lds32(uint32_t a){
    uint32_t v;
    asm("ld.shared.b32 %0, [%1];" : "=r"(v) : "r"(a));
    return v;
}
__device__ __forceinline__ float4 lds128f(uint32_t a){
    float4 v;
    asm volatile("ld.shared.v4.f32 {%0,%1,%2,%3}, [%4];"
                 : "=f"(v.x), "=f"(v.y), "=f"(v.z), "=f"(v.w) : "r"(a));
    return v;
}
__device__ __forceinline__ void cp16(uint32_t dst, const void* src){
    asm volatile("cp.async.cg.shared.global [%0], [%1], 16;" :: "r"(dst), "l"(src));
}
__device__ __forceinline__ void mma_tf32(float* c,
                                         uint32_t a0, uint32_t a1, uint32_t a2, uint32_t a3,
                                         uint32_t b0, uint32_t b1){
    asm volatile(
        "mma.sync.aligned.m16n8k8.row.col.f32.tf32.tf32.f32 "
        "{%0,%1,%2,%3}, {%4,%5,%6,%7}, {%8,%9}, {%0,%1,%2,%3};"
        : "+f"(c[0]), "+f"(c[1]), "+f"(c[2]), "+f"(c[3])
        : "r"(a0), "r"(a1), "r"(a2), "r"(a3), "r"(b0), "r"(b1));
}

// ---------------- prep: zero acc, sq[j] exact, XT tf32 ----------------
__global__ void __launch_bounds__(256) k_prep(const float* __restrict__ X){
    __shared__ float tile[64*129];
    int tid = threadIdx.x;
    int j0 = blockIdx.x * 64;
    if (blockIdx.x == 0 && tid < 3) g_acc[tid] = 0.0;
#pragma unroll
    for (int p = 0; p < 8; ++p){
        int idx = p*256 + tid;
        int r = idx >> 5;
        int c = idx & 31;
        float4 v = ((const float4*)(X + (size_t)(j0 + r)*DDIM))[c];
        tile[r*129 + c*4 + 0] = v.x;
        tile[r*129 + c*4 + 1] = v.y;
        tile[r*129 + c*4 + 2] = v.z;
        tile[r*129 + c*4 + 3] = v.w;
    }
    __syncthreads();
    if (tid < 64){
        float s = 0.f;
        const float* row = tile + tid*129;
#pragma unroll 8
        for (int c = 0; c < 128; ++c) s += row[c]*row[c];
        g_sq[j0 + tid] = s;
    }
#pragma unroll
    for (int p = 0; p < 8; ++p){
        int u  = p*256 + tid;
        int d  = u >> 4;
        int ju = (u & 15) * 4;
        uint4 o;
        o.x = f2tf32(tile[(ju+0)*129 + d]);
        o.y = f2tf32(tile[(ju+1)*129 + d]);
        o.z = f2tf32(tile[(ju+2)*129 + d]);
        o.w = f2tf32(tile[(ju+3)*129 + d]);
        *(uint4*)(g_XT + (size_t)d*NROWS + j0 + ju) = o;
    }
}

// ---------------- main: GEMM blocks 0..127 (A = L^T streamed k-major), CE 128..147 ----------------
__global__ void __launch_bounds__(NTHR, 1)
k_main(const float* __restrict__ L, const float* __restrict__ X,
       const float* __restrict__ preds, const int* __restrict__ tgt){
    extern __shared__ __align__(16) char dyn[];
    __shared__ float s_red[32];
    int tid = threadIdx.x, wid = tid>>5, lane = tid&31;

    if (blockIdx.x >= NGEMM){
        // ---- cross-entropy: 20 CTAs x 16 warps ----
        int g = (blockIdx.x - NGEMM)*16 + wid;
        float ce = 0.f;
        for (int r = g; r < NROWS; r += NCE*16){
            const float4* row4 = (const float4*)(preds + (size_t)r*NCLS);
            float s = 0.f;
            for (int c4 = lane; c4 < NCLS/4; c4 += 32){
                float4 v = __ldg(row4 + c4);
                s += __expf(v.x) + __expf(v.y) + __expf(v.z) + __expf(v.w);
            }
#pragma unroll
            for (int o = 16; o; o >>= 1) s += __shfl_xor_sync(~0u, s, o);
            if (lane == 0)
                ce += __logf(s) - __ldg(preds + (size_t)r*NCLS + __ldg(tgt + r));
        }
        if (lane == 0) atomicAdd(&g_acc[0], (double)ce);
        return;
    }

    // ---- GEMM (D = L^T X restricted to tile) + fused T ----
    uint32_t base = smem_u32(dyn);
    int m0 = (blockIdx.x >> 1) * 128;
    int k0 = (blockIdx.x & 1) * KRANGE;

    // A loader: thread -> k-row kl = tid>>3 (0..63), slot s = tid&7; 4 x cp16 of contiguous L[k][m-band]
    int kl = tid >> 3, sa = tid & 7;
    const float* ApRow = L + (size_t)kl*NROWS + m0 + sa*4;   // + (k0 + c*KCH)*NROWS advances per chunk
    uint32_t aDst = (uint32_t)(kl*ASTRIDE + sa*4)*4;         // bytes within A stage
    // B loader: thread -> d-row db = tid>>2 (0..127), slot sb = tid&3; 4 x cp16
    int db = tid >> 2, sb = tid & 3;
    const float* BpRow = g_XT + (size_t)db*NROWS + k0 + sb*4;
    uint32_t bDst = ABYTES + (uint32_t)(db*BSTRIDE + sb*4)*4;

    // sq for T term: per-chunk sq_k (scalar LDG), per-thread sq_m vector (preload)
    float4 sqm[4];
#pragma unroll
    for (int q = 0; q < 4; ++q)
        sqm[q] = __ldg((const float4*)(g_sq + m0) + sa + q*8);

    // prologue: stages 0,1
#pragma unroll
    for (int s = 0; s < NSTAGE-1; ++s){
        size_t ka = (size_t)(k0 + s*KCH)*NROWS;
        uint32_t sbase = base + s*STAGEB;
#pragma unroll
        for (int q = 0; q < 4; ++q){
            cp16(sbase + aDst + q*128, ApRow + ka + q*32);
            cp16(sbase + bDst + q*64,  BpRow + s*KCH + q*16);
        }
        asm volatile("cp.async.commit_group;" ::: "memory");
    }

    // warp tiling: 4 (M) x 4 (N), warp tile 32x32
    int warp_m = wid >> 2, warp_n = wid & 3;
    int r = lane >> 2, cg = lane & 3;
    // A frags from k-major smem: addr = (k8+cg[+4])*544 + (warp_m*32 + tm*16 + r [+8])*4
    uint32_t aAm = (uint32_t)(warp_m*32 + r)*4;
    uint32_t aBn = ABYTES + (uint32_t)((warp_n*32 + r)*BSTRIDE + cg)*4;

    float acc[2][4][4];
#pragma unroll
    for (int i = 0; i < 2; ++i)
#pragma unroll
        for (int j = 0; j < 4; ++j)
#pragma unroll
            for (int q = 0; q < 4; ++q) acc[i][j][q] = 0.f;
    float tloc = 0.f;

#pragma unroll 1
    for (int c = 0; c < NCHUNK; ++c){
        asm volatile("cp.async.wait_group %0;" :: "n"(NSTAGE-2) : "memory");
        __syncthreads();

        int cn = c + NSTAGE - 1;
        if (cn < NCHUNK){
            size_t ka = (size_t)(k0 + cn*KCH)*NROWS;
            uint32_t sbase = base + (cn % NSTAGE)*STAGEB;
#pragma unroll
            for (int q = 0; q < 4; ++q){
                cp16(sbase + aDst + q*128, ApRow + ka + q*32);
                cp16(sbase + bDst + q*64,  BpRow + cn*KCH + q*16);
            }
        }
        asm volatile("cp.async.commit_group;" ::: "memory");

        uint32_t sbase = base + (c % NSTAGE)*STAGEB;

        // fused T: readback this thread's A row band; T += L[k][m]*(sq_k + sq_m)
        {
            float sqk = __ldg(g_sq + k0 + c*KCH + kl);
            uint32_t ta = sbase + aDst;
#pragma unroll
            for (int q = 0; q < 4; ++q){
                float4 v = lds128f(ta + q*128);
                tloc += (v.x+v.y+v.z+v.w)*sqk
                      + v.x*sqm[q].x + v.y*sqm[q].y + v.z*sqm[q].z + v.w*sqm[q].w;
            }
        }

        // MMA over buffer c (A = raw fp32 bits; HW truncates to tf32)
        uint32_t bA = sbase + aAm;
        uint32_t bB = sbase + aBn;
#pragma unroll
        for (int k8 = 0; k8 < KCH; k8 += 8){
            uint32_t af[2][4], bf[4][2];
            uint32_t rowk0 = (uint32_t)(k8 + cg)*(ASTRIDE*4);
            uint32_t rowk1 = rowk0 + 4*(ASTRIDE*4);
#pragma unroll
            for (int tm = 0; tm < 2; ++tm){
                uint32_t p0 = bA + rowk0 + tm*64;
                uint32_t p1 = bA + rowk1 + tm*64;
                af[tm][0] = lds32(p0);
                af[tm][1] = lds32(p0 + 32);
                af[tm][2] = lds32(p1);
                af[tm][3] = lds32(p1 + 32);
            }
#pragma unroll
            for (int tn = 0; tn < 4; ++tn){
                uint32_t p = bB + (uint32_t)(tn*8*BSTRIDE + k8)*4;
                bf[tn][0] = lds32(p);
                bf[tn][1] = lds32(p + 16);
            }
#pragma unroll
            for (int tm = 0; tm < 2; ++tm)
#pragma unroll
                for (int tn = 0; tn < 4; ++tn)
                    mma_tf32(acc[tm][tn], af[tm][0], af[tm][1], af[tm][2], af[tm][3],
                             bf[tn][0], bf[tn][1]);
        }
    }

    // epilogue: cross += acc .* X (exact fp32); D[m][n] layout standard
    float cpart = 0.f;
#pragma unroll
    for (int tm = 0; tm < 2; ++tm){
#pragma unroll
        for (int tn = 0; tn < 4; ++tn){
#pragma unroll
            for (int q = 0; q < 4; ++q){
                int mrow = m0 + warp_m*32 + tm*16 + r + ((q>>1)<<3);
                int ncol = warp_n*32 + tn*8 + cg*2 + (q&1);
                cpart += acc[tm][tn][q] * __ldg(X + (size_t)mrow*DDIM + ncol);
            }
        }
    }

#pragma unroll
    for (int o = 16; o; o >>= 1){
        tloc  += __shfl_xor_sync(~0u, tloc,  o);
        cpart += __shfl_xor_sync(~0u, cpart, o);
    }
    if (lane == 0){ s_red[wid] = tloc; s_red[16 + wid] = cpart; }
    __syncthreads();
    if (tid == 0){
        float ts = 0.f, cs = 0.f;
#pragma unroll
        for (int w = 0; w < 16; ++w){ ts += s_red[w]; cs += s_red[16 + w]; }
        atomicAdd(&g_acc[1], (double)ts);
        atomicAdd(&g_acc[2], (double)cs);
    }
}

__global__ void k_final(float* out, int n){
    double v = g_acc[0] / (double)NROWS + 0.1 * (g_acc[1] - 2.0 * g_acc[2]);
    for (int i = threadIdx.x; i < n; i += blockDim.x) out[i] = (float)v;
}

// no-op: shifts profiler launch parity so ncu -s 5 lands on k_main
__global__ void k_nop(){ }

extern "C" void kernel_launch(void* const* d_in, const int* in_sizes, int n_in,
                              void* d_out, int out_size){
    const float* preds = (const float*)d_in[0];
    const int*   tgt   = (const int*)d_in[1];
    const float* L     = (const float*)d_in[2];
    const float* X     = (const float*)d_in[3];
    float* out = (float*)d_out;
    (void)in_sizes; (void)n_in;

    cudaFuncSetAttribute((const void*)k_main, cudaFuncAttributeMaxDynamicSharedMemorySize, DYN_BYTES);

    k_prep<<<NROWS/64, 256>>>(X);
    k_main<<<NGEMM + NCE, NTHR, DYN_BYTES>>>(L, X, preds, tgt);
    k_final<<<1, 256>>>(out, out_size);
    k_nop<<<1, 32>>>();
}

// round 13
// speedup vs baseline: 1.3244x; 1.0687x over previous
#include <cuda_runtime.h>
#include <cstdint>

#define NROWS 8192
#define DDIM  128
#define NCLS  1000
#define KSPLIT 4
#define KRANGE (NROWS/KSPLIT)  // 2048
#define KCH   64
#define NCHUNK (KRANGE/KCH)    // 32
#define NSTAGE 2
#define MTILE 256
// A smem: k-major, 64 k-rows x 264 floats (256 m + 8 pad) = 1056B/row -> 67584B
#define ASTRIDE 264
#define ABYTES  (KCH*ASTRIDE*4)
// B smem: d-major, 128 d-rows x 68 floats (64 k + 4 pad) = 272B/row -> 34816B
#define BSTRIDE 68
#define BBYTES  (128*BSTRIDE*4)
#define STAGEB  (ABYTES + BBYTES)       // 102400
#define DYN_BYTES (NSTAGE*STAGEB)       // 204800
#define NGEMM 128              // 32 mtiles x 4 ksplits
#define NCE   20
#define NTHR  512

__device__ __align__(16) float g_XT[(size_t)DDIM*NROWS];  // tf32-rounded X^T [d][j]
__device__ float  g_sq[NROWS];
__device__ double g_acc[3];   // 0: ce-sum  1: T  2: cross

// ---------------- helpers ----------------
__device__ __forceinline__ uint32_t smem_u32(const void* p){
    uint32_t a;
    asm("{ .reg .u64 t; cvta.to.shared.u64 t, %1; cvt.u32.u64 %0, t; }" : "=r"(a) : "l"(p));
    return a;
}
__device__ __forceinline__ uint32_t f2tf32(float x){
    uint32_t u;
    asm("cvt.rna.tf32.f32 %0, %1;" : "=r"(u) : "f"(x));
    return u;
}
__device__ __forceinline__ uint32_t lds32(uint32_t a){
    uint32_t v;
    asm("ld.shared.b32 %0, [%1];" : "=r"(v) : "r"(a));
    return v;
}
__device__ __forceinline__ void cp16(uint32_t dst, const void* src){
    asm volatile("cp.async.cg.shared.global [%0], [%1], 16;" :: "r"(dst), "l"(src));
}
__device__ __forceinline__ void mma_tf32(float* c,
                                         uint32_t a0, uint32_t a1, uint32_t a2, uint32_t a3,
                                         uint32_t b0, uint32_t b1){
    asm volatile(
        "mma.sync.aligned.m16n8k8.row.col.f32.tf32.tf32.f32 "
        "{%0,%1,%2,%3}, {%4,%5,%6,%7}, {%8,%9}, {%0,%1,%2,%3};"
        : "+f"(c[0]), "+f"(c[1]), "+f"(c[2]), "+f"(c[3])
        : "r"(a0), "r"(a1), "r"(a2), "r"(a3), "r"(b0), "r"(b1));
}

// ---------------- prep: zero acc, sq[j] exact, XT tf32 ----------------
__global__ void __launch_bounds__(256) k_prep(const float* __restrict__ X){
    __shared__ float tile[64*129];
    int tid = threadIdx.x;
    int j0 = blockIdx.x * 64;
    if (blockIdx.x == 0 && tid < 3) g_acc[tid] = 0.0;
#pragma unroll
    for (int p = 0; p < 8; ++p){
        int idx = p*256 + tid;
        int r = idx >> 5;
        int c = idx & 31;
        float4 v = ((const float4*)(X + (size_t)(j0 + r)*DDIM))[c];
        tile[r*129 + c*4 + 0] = v.x;
        tile[r*129 + c*4 + 1] = v.y;
        tile[r*129 + c*4 + 2] = v.z;
        tile[r*129 + c*4 + 3] = v.w;
    }
    __syncthreads();
    if (tid < 64){
        float s = 0.f;
        const float* row = tile + tid*129;
#pragma unroll 8
        for (int c = 0; c < 128; ++c) s += row[c]*row[c];
        g_sq[j0 + tid] = s;
    }
#pragma unroll
    for (int p = 0; p < 8; ++p){
        int u  = p*256 + tid;
        int d  = u >> 4;
        int ju = (u & 15) * 4;
        uint4 o;
        o.x = f2tf32(tile[(ju+0)*129 + d]);
        o.y = f2tf32(tile[(ju+1)*129 + d]);
        o.z = f2tf32(tile[(ju+2)*129 + d]);
        o.w = f2tf32(tile[(ju+3)*129 + d]);
        *(uint4*)(g_XT + (size_t)d*NROWS + j0 + ju) = o;
    }
}

// ---------------- main: GEMM blocks 0..127 (CTA tile 256x128, A = L^T k-major), CE 128..147 ----------------
__global__ void __launch_bounds__(NTHR, 1)
k_main(const float* __restrict__ L, const float* __restrict__ X,
       const float* __restrict__ preds, const int* __restrict__ tgt){
    extern __shared__ __align__(16) char dyn[];
    __shared__ float s_red[32];
    int tid = threadIdx.x, wid = tid>>5, lane = tid&31;

    if (blockIdx.x >= NGEMM){
        // ---- cross-entropy: 20 CTAs x 16 warps ----
        int g = (blockIdx.x - NGEMM)*16 + wid;
        float ce = 0.f;
        for (int r = g; r < NROWS; r += NCE*16){
            const float4* row4 = (const float4*)(preds + (size_t)r*NCLS);
            float s = 0.f;
            for (int c4 = lane; c4 < NCLS/4; c4 += 32){
                float4 v = __ldg(row4 + c4);
                s += __expf(v.x) + __expf(v.y) + __expf(v.z) + __expf(v.w);
            }
#pragma unroll
            for (int o = 16; o; o >>= 1) s += __shfl_xor_sync(~0u, s, o);
            if (lane == 0)
                ce += __logf(s) - __ldg(preds + (size_t)r*NCLS + __ldg(tgt + r));
        }
        if (lane == 0) atomicAdd(&g_acc[0], (double)ce);
        return;
    }

    // ---- GEMM (D = L^T X on tile) + fused T ----
    uint32_t base = smem_u32(dyn);
    int m0 = (blockIdx.x >> 2) * MTILE;
    int k0 = (blockIdx.x & 3) * KRANGE;

    // A loader: kl = tid>>3 (0..63), sa = tid&7; 8 x cp16 covering 256 m-floats of one k-row
    int kl = tid >> 3, sa = tid & 7;
    const float* ApRow = L + m0 + sa*4;                 // + (k0+c*KCH+kl)*NROWS per chunk
    uint32_t aDst = (uint32_t)(kl*ASTRIDE + sa*4)*4;
    // B loader: db = tid>>2 (0..127), sb = tid&3; 4 x cp16
    int db = tid >> 2, sb = tid & 3;
    const float* BpRow = g_XT + (size_t)db*NROWS + k0 + sb*4;
    uint32_t bDst = ABYTES + (uint32_t)(db*BSTRIDE + sb*4)*4;

    // prologue: stage 0
    {
        size_t ka = ((size_t)k0 + kl)*NROWS;
#pragma unroll
        for (int q = 0; q < 8; ++q) cp16(base + aDst + q*128, ApRow + ka + q*32);
#pragma unroll
        for (int q = 0; q < 4; ++q) cp16(base + bDst + q*64, BpRow + q*16);
        asm volatile("cp.async.commit_group;" ::: "memory");
    }

    // warp tiling: 4 (M) x 4 (N), warp tile 64x32
    int warp_m = wid >> 2, warp_n = wid & 3;
    int r = lane >> 2, cg = lane & 3;
    uint32_t aAm = (uint32_t)(warp_m*64 + r)*4;
    uint32_t aBn = ABYTES + (uint32_t)((warp_n*32 + r)*BSTRIDE + cg)*4;

    float acc[4][4][4];
#pragma unroll
    for (int i = 0; i < 4; ++i)
#pragma unroll
        for (int j = 0; j < 4; ++j)
#pragma unroll
            for (int q = 0; q < 4; ++q) acc[i][j][q] = 0.f;
    float tloc = 0.f;

#pragma unroll 1
    for (int c = 0; c < NCHUNK; ++c){
        asm volatile("cp.async.wait_group 0;" ::: "memory");
        __syncthreads();

        int cn = c + 1;
        if (cn < NCHUNK){
            size_t ka = ((size_t)(k0 + cn*KCH) + kl)*NROWS;
            uint32_t sb2 = base + (cn & 1)*STAGEB;
#pragma unroll
            for (int q = 0; q < 8; ++q) cp16(sb2 + aDst + q*128, ApRow + ka + q*32);
#pragma unroll
            for (int q = 0; q < 4; ++q) cp16(sb2 + bDst + q*64, BpRow + cn*KCH + q*16);
        }
        asm volatile("cp.async.commit_group;" ::: "memory");

        uint32_t sbase = base + (c & 1)*STAGEB;

        // fused T via LDG re-read (L2-hot; off crossbar): T += L[k][m]*(sq_k + sq_m)
        {
            const float* lr = L + ((size_t)(k0 + c*KCH) + kl)*NROWS + m0 + sa*4;
            float sqk = __ldg(g_sq + k0 + c*KCH + kl);
#pragma unroll
            for (int q = 0; q < 8; ++q){
                float4 v = __ldg((const float4*)(lr + q*32));
                float4 s4 = __ldg((const float4*)(g_sq + m0) + sa + q*8);
                tloc += (v.x+v.y+v.z+v.w)*sqk
                      + v.x*s4.x + v.y*s4.y + v.z*s4.z + v.w*s4.w;
            }
        }

        // MMA over buffer c (A = raw fp32 bits; HW truncates to tf32)
        uint32_t bA = sbase + aAm;
        uint32_t bB = sbase + aBn;
#pragma unroll
        for (int k8 = 0; k8 < KCH; k8 += 8){
            uint32_t af[4][4], bf[4][2];
            uint32_t rowk0 = (uint32_t)(k8 + cg)*(ASTRIDE*4);
            uint32_t rowk1 = rowk0 + 4*(ASTRIDE*4);
#pragma unroll
            for (int tm = 0; tm < 4; ++tm){
                uint32_t p0 = bA + rowk0 + tm*64;
                uint32_t p1 = bA + rowk1 + tm*64;
                af[tm][0] = lds32(p0);
                af[tm][1] = lds32(p0 + 32);
                af[tm][2] = lds32(p1);
                af[tm][3] = lds32(p1 + 32);
            }
#pragma unroll
            for (int tn = 0; tn < 4; ++tn){
                uint32_t p = bB + (uint32_t)(tn*8*BSTRIDE + k8)*4;
                bf[tn][0] = lds32(p);
                bf[tn][1] = lds32(p + 16);
            }
#pragma unroll
            for (int tm = 0; tm < 4; ++tm)
#pragma unroll
                for (int tn = 0; tn < 4; ++tn)
                    mma_tf32(acc[tm][tn], af[tm][0], af[tm][1], af[tm][2], af[tm][3],
                             bf[tn][0], bf[tn][1]);
        }
    }

    // epilogue: cross += acc .* X (exact fp32)
    float cpart = 0.f;
#pragma unroll
    for (int tm = 0; tm < 4; ++tm){
#pragma unroll
        for (int tn = 0; tn < 4; ++tn){
#pragma unroll
            for (int q = 0; q < 4; ++q){
                int mrow = m0 + warp_m*64 + tm*16 + r + ((q>>1)<<3);
                int ncol = warp_n*32 + tn*8 + cg*2 + (q&1);
                cpart += acc[tm][tn][q] * __ldg(X + (size_t)mrow*DDIM + ncol);
            }
        }
    }

#pragma unroll
    for (int o = 16; o; o >>= 1){
        tloc  += __shfl_xor_sync(~0u, tloc,  o);
        cpart += __shfl_xor_sync(~0u, cpart, o);
    }
    if (lane == 0){ s_red[wid] = tloc; s_red[16 + wid] = cpart; }
    __syncthreads();
    if (tid == 0){
        float ts = 0.f, cs = 0.f;
#pragma unroll
        for (int w = 0; w < 16; ++w){ ts += s_red[w]; cs += s_red[16 + w]; }
        atomicAdd(&g_acc[1], (double)ts);
        atomicAdd(&g_acc[2], (double)cs);
    }
}

__global__ void k_final(float* out, int n){
    double v = g_acc[0] / (double)NROWS + 0.1 * (g_acc[1] - 2.0 * g_acc[2]);
    for (int i = threadIdx.x; i < n; i += blockDim.x) out[i] = (float)v;
}

__global__ void k_nop(){ }

extern "C" void kernel_launch(void* const* d_in, const int* in_sizes, int n_in,
                              void* d_out, int out_size){
    const float* preds = (const float*)d_in[0];
    const int*   tgt   = (const int*)d_in[1];
    const float* L     = (const float*)d_in[2];
    const float* X     = (const float*)d_in[3];
    float* out = (float*)d_out;
    (void)in_sizes; (void)n_in;

    cudaFuncSetAttribute((const void*)k_main, cudaFuncAttributeMaxDynamicSharedMemorySize, DYN_BYTES);

    // launch idx 3 = k_main (ncu capture lands on idx 3; see R7/R8-10/R12 parity evidence)
    k_prep<<<NROWS/64, 256>>>(X);                       // 0
    k_nop<<<1, 32>>>();                                 // 1
    k_nop<<<1, 32>>>();                                 // 2
    k_main<<<NGEMM + NCE, NTHR, DYN_BYTES>>>(L, X, preds, tgt);  // 3
    k_final<<<1, 256>>>(out, out_size);                 // 4
}

// round 14
// speedup vs baseline: 1.4723x; 1.1117x over previous
#include <cuda_runtime.h>
#include <cstdint>

#define NROWS 8192
#define DDIM  128
#define NCLS  1000
#define KSPLIT 4
#define KRANGE (NROWS/KSPLIT)  // 2048
#define KCH   32
#define NCHUNK (KRANGE/KCH)    // 64
#define NSTAGE 4
#define MTILE 256
// A smem: k-major, 32 k-rows x 260 floats (256 m + 4 pad) = 1040B/row -> 33280B
#define ASTRIDE 260
#define ABYTES  (KCH*ASTRIDE*4)        // 33280
// B smem: d-major, 128 d-rows x 40 floats (32 k + 8 pad) = 160B/row -> 20480B
#define BSTRIDE 40
#define BBYTES  (128*BSTRIDE*4)        // 20480
#define STAGEB  (ABYTES + BBYTES)      // 53760
#define DYN_BYTES (NSTAGE*STAGEB)      // 215040
#define NGEMM 128              // 32 mtiles x 4 ksplits
#define NCE   20
#define NTHR  512

__device__ __align__(16) float g_XT[(size_t)DDIM*NROWS];  // tf32-rounded X^T [d][j]
__device__ float  g_sq[NROWS];
__device__ double g_acc[3];   // 0: ce-sum  1: T  2: cross

// ---------------- helpers ----------------
__device__ __forceinline__ uint32_t smem_u32(const void* p){
    uint32_t a;
    asm("{ .reg .u64 t; cvta.to.shared.u64 t, %1; cvt.u32.u64 %0, t; }" : "=r"(a) : "l"(p));
    return a;
}
__device__ __forceinline__ uint32_t f2tf32(float x){
    uint32_t u;
    asm("cvt.rna.tf32.f32 %0, %1;" : "=r"(u) : "f"(x));
    return u;
}
__device__ __forceinline__ uint32_t lds32(uint32_t a){
    uint32_t v;
    asm("ld.shared.b32 %0, [%1];" : "=r"(v) : "r"(a));
    return v;
}
__device__ __forceinline__ void lds64(uint32_t a, uint32_t& lo, uint32_t& hi){
    asm volatile("ld.shared.v2.b32 {%0,%1}, [%2];" : "=r"(lo), "=r"(hi) : "r"(a));
}
__device__ __forceinline__ float4 lds128f(uint32_t a){
    float4 v;
    asm volatile("ld.shared.v4.f32 {%0,%1,%2,%3}, [%4];"
                 : "=f"(v.x), "=f"(v.y), "=f"(v.z), "=f"(v.w) : "r"(a));
    return v;
}
__device__ __forceinline__ void cp16(uint32_t dst, const void* src){
    asm volatile("cp.async.cg.shared.global [%0], [%1], 16;" :: "r"(dst), "l"(src));
}
__device__ __forceinline__ void mma_tf32(float* c,
                                         uint32_t a0, uint32_t a1, uint32_t a2, uint32_t a3,
                                         uint32_t b0, uint32_t b1){
    asm volatile(
        "mma.sync.aligned.m16n8k8.row.col.f32.tf32.tf32.f32 "
        "{%0,%1,%2,%3}, {%4,%5,%6,%7}, {%8,%9}, {%0,%1,%2,%3};"
        : "+f"(c[0]), "+f"(c[1]), "+f"(c[2]), "+f"(c[3])
        : "r"(a0), "r"(a1), "r"(a2), "r"(a3), "r"(b0), "r"(b1));
}

// ---------------- prep: zero acc, sq[j] exact, XT tf32 ----------------
__global__ void __launch_bounds__(256) k_prep(const float* __restrict__ X){
    __shared__ float tile[64*129];
    int tid = threadIdx.x;
    int j0 = blockIdx.x * 64;
    if (blockIdx.x == 0 && tid < 3) g_acc[tid] = 0.0;
#pragma unroll
    for (int p = 0; p < 8; ++p){
        int idx = p*256 + tid;
        int r = idx >> 5;
        int c = idx & 31;
        float4 v = ((const float4*)(X + (size_t)(j0 + r)*DDIM))[c];
        tile[r*129 + c*4 + 0] = v.x;
        tile[r*129 + c*4 + 1] = v.y;
        tile[r*129 + c*4 + 2] = v.z;
        tile[r*129 + c*4 + 3] = v.w;
    }
    __syncthreads();
    if (tid < 64){
        float s = 0.f;
        const float* row = tile + tid*129;
#pragma unroll 8
        for (int c = 0; c < 128; ++c) s += row[c]*row[c];
        g_sq[j0 + tid] = s;
    }
#pragma unroll
    for (int p = 0; p < 8; ++p){
        int u  = p*256 + tid;
        int d  = u >> 4;
        int ju = (u & 15) * 4;
        uint4 o;
        o.x = f2tf32(tile[(ju+0)*129 + d]);
        o.y = f2tf32(tile[(ju+1)*129 + d]);
        o.z = f2tf32(tile[(ju+2)*129 + d]);
        o.w = f2tf32(tile[(ju+3)*129 + d]);
        *(uint4*)(g_XT + (size_t)d*NROWS + j0 + ju) = o;
    }
}

// ---------------- main: GEMM blocks 0..127 (CTA tile 256x128, A = L^T k-major), CE 128..147 ----------------
__global__ void __launch_bounds__(NTHR, 1)
k_main(const float* __restrict__ L, const float* __restrict__ X,
       const float* __restrict__ preds, const int* __restrict__ tgt){
    extern __shared__ __align__(16) char dyn[];
    __shared__ float s_red[32];
    int tid = threadIdx.x, wid = tid>>5, lane = tid&31;

    if (blockIdx.x >= NGEMM){
        // ---- cross-entropy: 20 CTAs x 16 warps ----
        int g = (blockIdx.x - NGEMM)*16 + wid;
        float ce = 0.f;
        for (int r = g; r < NROWS; r += NCE*16){
            const float4* row4 = (const float4*)(preds + (size_t)r*NCLS);
            float s = 0.f;
            for (int c4 = lane; c4 < NCLS/4; c4 += 32){
                float4 v = __ldg(row4 + c4);
                s += __expf(v.x) + __expf(v.y) + __expf(v.z) + __expf(v.w);
            }
#pragma unroll
            for (int o = 16; o; o >>= 1) s += __shfl_xor_sync(~0u, s, o);
            if (lane == 0)
                ce += __logf(s) - __ldg(preds + (size_t)r*NCLS + __ldg(tgt + r));
        }
        if (lane == 0) atomicAdd(&g_acc[0], (double)ce);
        return;
    }

    // ---- GEMM (D = L^T X on tile) + fused T ----
    uint32_t base = smem_u32(dyn);
    int m0 = (blockIdx.x >> 2) * MTILE;
    int k0 = (blockIdx.x & 3) * KRANGE;

    // A loader: kl = tid>>4 (0..31), sa = tid&15; 4 x cp16 covering 256 m-floats of one k-row
    int kl = tid >> 4, sa = tid & 15;
    const float* ApRow = L + m0 + sa*4;              // + (k0+c*KCH+kl)*NROWS per chunk; q stride 64 floats
    uint32_t aDst = (uint32_t)kl*(ASTRIDE*4) + (uint32_t)sa*16;   // q stride 256 B
    // B loader: db = tid>>2 (0..127), sb = tid&3; 2 x cp16
    int db = tid >> 2, sb = tid & 3;
    const float* BpRow = g_XT + (size_t)db*NROWS + k0 + sb*4;     // q stride 16 floats
    uint32_t bDst = ABYTES + (uint32_t)db*(BSTRIDE*4) + (uint32_t)sb*16;  // q stride 64 B

    // prologue: stages 0..NSTAGE-2
#pragma unroll
    for (int s = 0; s < NSTAGE-1; ++s){
        size_t ka = ((size_t)(k0 + s*KCH) + kl)*NROWS;
        uint32_t sb2 = base + s*STAGEB;
#pragma unroll
        for (int q = 0; q < 4; ++q) cp16(sb2 + aDst + q*256, ApRow + ka + q*64);
#pragma unroll
        for (int q = 0; q < 2; ++q) cp16(sb2 + bDst + q*64, BpRow + s*KCH + q*16);
        asm volatile("cp.async.commit_group;" ::: "memory");
    }

    // warp tiling: 4 (M) x 4 (N), warp tile 64x32
    int warp_m = wid >> 2, warp_n = wid & 3;
    int r = lane >> 2, cg = lane & 3;
    uint32_t aAm = (uint32_t)(warp_m*64 + r)*4;
    uint32_t aBn = ABYTES + (uint32_t)((warp_n*32 + r)*BSTRIDE + 2*cg)*4;

    float acc[4][4][4];
#pragma unroll
    for (int i = 0; i < 4; ++i)
#pragma unroll
        for (int j = 0; j < 4; ++j)
#pragma unroll
            for (int q = 0; q < 4; ++q) acc[i][j][q] = 0.f;
    float tloc = 0.f;

#pragma unroll 1
    for (int c = 0; c < NCHUNK; ++c){
        asm volatile("cp.async.wait_group %0;" :: "n"(NSTAGE-2) : "memory");
        __syncthreads();

        int cn = c + NSTAGE - 1;
        if (cn < NCHUNK){
            size_t ka = ((size_t)(k0 + cn*KCH) + kl)*NROWS;
            uint32_t sb2 = base + (cn & (NSTAGE-1))*STAGEB;
#pragma unroll
            for (int q = 0; q < 4; ++q) cp16(sb2 + aDst + q*256, ApRow + ka + q*64);
#pragma unroll
            for (int q = 0; q < 2; ++q) cp16(sb2 + bDst + q*64, BpRow + cn*KCH + q*16);
        }
        asm volatile("cp.async.commit_group;" ::: "memory");

        uint32_t sbase = base + (c & (NSTAGE-1))*STAGEB;

        // fused T via smem readback: T += L[k][m]*(sq_k + sq_m)
        {
            float sqk = __ldg(g_sq + k0 + c*KCH + kl);
            uint32_t ta = sbase + aDst;
#pragma unroll
            for (int q = 0; q < 4; ++q){
                float4 v  = lds128f(ta + q*256);
                float4 s4 = __ldg((const float4*)(g_sq + m0) + sa + q*16);
                tloc += (v.x+v.y+v.z+v.w)*sqk
                      + v.x*s4.x + v.y*s4.y + v.z*s4.z + v.w*s4.w;
            }
        }

        // MMA over buffer c (A = raw fp32 bits; HW truncates to tf32)
        // k-permutation: slot cg -> physical k8+2cg, slot cg+4 -> k8+2cg+1 (both operands)
        uint32_t bA = sbase + aAm;
        uint32_t bB = sbase + aBn;
#pragma unroll
        for (int k8 = 0; k8 < KCH; k8 += 8){
            uint32_t af[4][4], bf[4][2];
            uint32_t rowk0 = ((uint32_t)k8 + 2*(uint32_t)cg)*(ASTRIDE*4);
            uint32_t rowk1 = rowk0 + (ASTRIDE*4);
#pragma unroll
            for (int tm = 0; tm < 4; ++tm){
                uint32_t p0 = bA + rowk0 + tm*64;
                uint32_t p1 = bA + rowk1 + tm*64;
                af[tm][0] = lds32(p0);          // slot cg,   m
                af[tm][1] = lds32(p0 + 32);     // slot cg,   m+8
                af[tm][2] = lds32(p1);          // slot cg+4, m
                af[tm][3] = lds32(p1 + 32);     // slot cg+4, m+8
            }
#pragma unroll
            for (int tn = 0; tn < 4; ++tn){
                uint32_t p = bB + (uint32_t)(tn*8*BSTRIDE + k8)*4;
                lds64(p, bf[tn][0], bf[tn][1]); // slots cg, cg+4 (phys 2cg, 2cg+1)
            }
#pragma unroll
            for (int tm = 0; tm < 4; ++tm)
#pragma unroll
                for (int tn = 0; tn < 4; ++tn)
                    mma_tf32(acc[tm][tn], af[tm][0], af[tm][1], af[tm][2], af[tm][3],
                             bf[tn][0], bf[tn][1]);
        }
    }

    // epilogue: cross += acc .* X (exact fp32)
    float cpart = 0.f;
#pragma unroll
    for (int tm = 0; tm < 4; ++tm){
#pragma unroll
        for (int tn = 0; tn < 4; ++tn){
#pragma unroll
            for (int q = 0; q < 4; ++q){
                int mrow = m0 + warp_m*64 + tm*16 + r + ((q>>1)<<3);
                int ncol = warp_n*32 + tn*8 + cg*2 + (q&1);
                cpart += acc[tm][tn][q] * __ldg(X + (size_t)mrow*DDIM + ncol);
            }
        }
    }

#pragma unroll
    for (int o = 16; o; o >>= 1){
        tloc  += __shfl_xor_sync(~0u, tloc,  o);
        cpart += __shfl_xor_sync(~0u, cpart, o);
    }
    if (lane == 0){ s_red[wid] = tloc; s_red[16 + wid] = cpart; }
    __syncthreads();
    if (tid == 0){
        float ts = 0.f, cs = 0.f;
#pragma unroll
        for (int w = 0; w < 16; ++w){ ts += s_red[w]; cs += s_red[16 + w]; }
        atomicAdd(&g_acc[1], (double)ts);
        atomicAdd(&g_acc[2], (double)cs);
    }
}

__global__ void k_final(float* out, int n){
    double v = g_acc[0] / (double)NROWS + 0.1 * (g_acc[1] - 2.0 * g_acc[2]);
    for (int i = threadIdx.x; i < n; i += blockDim.x) out[i] = (float)v;
}

__global__ void k_nop(){ }

extern "C" void kernel_launch(void* const* d_in, const int* in_sizes, int n_in,
                              void* d_out, int out_size){
    const float* preds = (const float*)d_in[0];
    const int*   tgt   = (const int*)d_in[1];
    const float* L     = (const float*)d_in[2];
    const float* X     = (const float*)d_in[3];
    float* out = (float*)d_out;
    (void)in_sizes; (void)n_in;

    cudaFuncSetAttribute((const void*)k_main, cudaFuncAttributeMaxDynamicSharedMemorySize, DYN_BYTES);

    // launch idx 3 = k_main (ncu capture lands on idx 3)
    k_prep<<<NROWS/64, 256>>>(X);                       // 0
    k_nop<<<1, 32>>>();                                 // 1
    k_nop<<<1, 32>>>();                                 // 2
    k_main<<<NGEMM + NCE, NTHR, DYN_BYTES>>>(L, X, preds, tgt);  // 3
    k_final<<<1, 256>>>(out, out_size);                 // 4
}